// round 2
// baseline (speedup 1.0000x reference)
#include <cuda_runtime.h>
#include <math.h>

#define T_SAMP   8388608
#define NFRAMES  16381
#define FFTLEN   2048
#define HOP      512
#define NBINS    84
#define FB       1025      // freq bins (fftLen/2+1)
#define K2       2050      // 2*FB (stacked cos/sin contraction dim)
#define WROWS    192       // 96 real rows (84 used) + 96 imag rows

// Fused time-domain CQT kernels: rows 0..95 = Wr[b], rows 96..191 = Wi[b]
__device__ float g_W[WROWS * FFTLEN];

// ---------------------------------------------------------------------------
// Precompute: g_W[192,2048] = A2[192,2050] @ B2[2050,2048]
//   A2[r,k]:  r<96 (real):  k<FB ? kr[r,k]   : -ki[r,k-FB]
//             r>=96 (imag): k<FB ? ki[r-96,k]:  kr[r-96,k-FB]
//             (rows with bin>=84 are zero padding)
//   B2[k,n]:  k<FB ? wcos[k,n] : wsin[k-FB,n]
// ---------------------------------------------------------------------------
#define PRE_TR 32
#define PRE_TC 64
#define PRE_TK 32

__global__ __launch_bounds__(256) void cqt_precompute_kernel(
    const float* __restrict__ wcos, const float* __restrict__ wsin,
    const float* __restrict__ kr,   const float* __restrict__ ki)
{
    __shared__ float As[PRE_TK][34];        // [k][row], stride 34 (even, padded)
    __shared__ float Bs[PRE_TK][PRE_TC];    // [k][col]

    const int tid  = threadIdx.x;
    const int cx   = tid & 15;              // 16 col groups x 4 cols
    const int ry   = tid >> 4;              // 16 row groups x 2 rows
    const int row0 = blockIdx.y * PRE_TR;
    const int col0 = blockIdx.x * PRE_TC;

    float acc[2][4] = {};

    for (int k0 = 0; k0 < K2; k0 += PRE_TK) {
        // stage A tile (32 rows x 32 k), coalesced over k
        for (int j = tid; j < PRE_TR * PRE_TK; j += 256) {
            int r  = j >> 5;
            int kk = j & 31;
            int grow = row0 + r;
            int gk   = k0 + kk;
            float v = 0.f;
            if (gk < K2) {
                int b = (grow < 96) ? grow : grow - 96;
                if (b < NBINS) {
                    if (grow < 96)
                        v = (gk < FB) ? kr[b * FB + gk] : -ki[b * FB + (gk - FB)];
                    else
                        v = (gk < FB) ? ki[b * FB + gk] :  kr[b * FB + (gk - FB)];
                }
            }
            As[kk][r] = v;
        }
        // stage B tile (32 k x 64 cols), coalesced over cols
        for (int j = tid; j < PRE_TK * PRE_TC; j += 256) {
            int kk = j >> 6;
            int cc = j & 63;
            int gk = k0 + kk;
            float v = 0.f;
            if (gk < K2) {
                v = (gk < FB) ? wcos[gk * FFTLEN + col0 + cc]
                              : wsin[(gk - FB) * FFTLEN + col0 + cc];
            }
            Bs[kk][cc] = v;
        }
        __syncthreads();
        #pragma unroll
        for (int kk = 0; kk < PRE_TK; kk++) {
            float2 a = *(const float2*)&As[kk][ry * 2];
            float4 b = *(const float4*)&Bs[kk][cx * 4];
            acc[0][0] += a.x * b.x; acc[0][1] += a.x * b.y;
            acc[0][2] += a.x * b.z; acc[0][3] += a.x * b.w;
            acc[1][0] += a.y * b.x; acc[1][1] += a.y * b.y;
            acc[1][2] += a.y * b.z; acc[1][3] += a.y * b.w;
        }
        __syncthreads();
    }

    #pragma unroll
    for (int rr = 0; rr < 2; rr++) {
        int grow = row0 + ry * 2 + rr;
        float4 v = make_float4(acc[rr][0], acc[rr][1], acc[rr][2], acc[rr][3]);
        *(float4*)&g_W[grow * FFTLEN + col0 + cx * 4] = v;
    }
}

// ---------------------------------------------------------------------------
// Main kernel: out[b,f] = |sum_n x[f*HOP+n] * (Wr + i Wi)[b,n]|
// Block: 32 frames (x span staged once in smem), all 84 bins.
// 128 threads = 4 frame-groups(x8) x 32 bin-cols(x3 bins strided by 32).
// ---------------------------------------------------------------------------
#define BM        32
#define KC        32
#define XS_LEN    ((BM - 1) * HOP + FFTLEN)   // 17920 floats
#define WS_STRIDE 36                          // lane stride == 4 mod 32 -> conflict-free
#define SMEM_MAIN ((XS_LEN + WROWS * WS_STRIDE) * 4)

__global__ __launch_bounds__(128) void cqt_main_kernel(
    const float* __restrict__ x, float* __restrict__ out)
{
    extern __shared__ float smem[];
    float* xs = smem;                 // XS_LEN
    float* ws = smem + XS_LEN;        // WROWS * WS_STRIDE

    const int tid = threadIdx.x;
    const int c   = tid & 31;         // bin column: bins c, c+32, c+64
    const int fg  = tid >> 5;         // frame group: frames fg*8 .. fg*8+7
    const int base = blockIdx.x * (BM * HOP);

    // stage x span once (vectorized, tail-guarded for the last block)
    for (int i = tid; i < XS_LEN / 4; i += 128) {
        int g = base + i * 4;
        float4 v;
        if (g + 3 < T_SAMP) {
            v = *(const float4*)&x[g];
        } else {
            v.x = (g + 0 < T_SAMP) ? x[g + 0] : 0.f;
            v.y = (g + 1 < T_SAMP) ? x[g + 1] : 0.f;
            v.z = (g + 2 < T_SAMP) ? x[g + 2] : 0.f;
            v.w = (g + 3 < T_SAMP) ? x[g + 3] : 0.f;
        }
        *(float4*)&xs[i * 4] = v;
    }

    float accR[8][3] = {};
    float accI[8][3] = {};

    for (int kc = 0; kc < FFTLEN; kc += KC) {
        __syncthreads();
        // stage W chunk: 192 rows x 32 k  (12 float4 per thread)
        for (int j = tid; j < WROWS * (KC / 4); j += 128) {
            int row = j >> 3;
            int kq  = j & 7;
            float4 v = *(const float4*)&g_W[row * FFTLEN + kc + kq * 4];
            *(float4*)&ws[row * WS_STRIDE + kq * 4] = v;
        }
        __syncthreads();

        #pragma unroll
        for (int k4 = 0; k4 < KC; k4 += 4) {
            float4 wr[3], wi[3];
            #pragma unroll
            for (int j = 0; j < 3; j++) {
                wr[j] = *(const float4*)&ws[(c + 32 * j) * WS_STRIDE + k4];
                wi[j] = *(const float4*)&ws[(96 + c + 32 * j) * WS_STRIDE + k4];
            }
            #pragma unroll
            for (int f = 0; f < 8; f++) {
                float4 xv = *(const float4*)&xs[(fg * 8 + f) * HOP + kc + k4];
                #pragma unroll
                for (int j = 0; j < 3; j++) {
                    accR[f][j] += xv.x * wr[j].x;
                    accR[f][j] += xv.y * wr[j].y;
                    accR[f][j] += xv.z * wr[j].z;
                    accR[f][j] += xv.w * wr[j].w;
                    accI[f][j] += xv.x * wi[j].x;
                    accI[f][j] += xv.y * wi[j].y;
                    accI[f][j] += xv.z * wi[j].z;
                    accI[f][j] += xv.w * wi[j].w;
                }
            }
        }
    }

    // epilogue: magnitude + scattered store (small: 5.5 MB total)
    #pragma unroll
    for (int f = 0; f < 8; f++) {
        int frame = blockIdx.x * BM + fg * 8 + f;
        if (frame >= NFRAMES) continue;
        #pragma unroll
        for (int j = 0; j < 3; j++) {
            int bin = c + 32 * j;
            if (bin < NBINS) {
                float r = accR[f][j], im = accI[f][j];
                out[bin * NFRAMES + frame] = sqrtf(r * r + im * im);
            }
        }
    }
}

// ---------------------------------------------------------------------------
extern "C" void kernel_launch(void* const* d_in, const int* in_sizes, int n_in,
                              void* d_out, int out_size)
{
    const float* x    = (const float*)d_in[0];
    const float* wcos = (const float*)d_in[1];
    const float* wsin = (const float*)d_in[2];
    const float* kr   = (const float*)d_in[3];
    const float* ki   = (const float*)d_in[4];
    float* out = (float*)d_out;

    (void)in_sizes; (void)n_in; (void)out_size;

    cudaFuncSetAttribute(cqt_main_kernel,
                         cudaFuncAttributeMaxDynamicSharedMemorySize, SMEM_MAIN);

    dim3 pre_grid(FFTLEN / PRE_TC, WROWS / PRE_TR);   // 32 x 6
    cqt_precompute_kernel<<<pre_grid, 256>>>(wcos, wsin, kr, ki);

    int nblocks = (NFRAMES + BM - 1) / BM;            // 512
    cqt_main_kernel<<<nblocks, 128, SMEM_MAIN>>>(x, out);
}